// round 1
// baseline (speedup 1.0000x reference)
#include <cuda_runtime.h>
#include <math.h>

// Precomputed per-interval cubic polynomial coefficients.
// 7 intervals (knot index i in [3,9]), each stores (a,b,c,d) for
// S(u) = ((a*u + b)*u + c)*u + d with u = 13*x - i.
__device__ float4 g_poly[7];

// ---------------------------------------------------------------------------
// Prologue: build the polynomial table from the 10 spline coefficients.
// Uniform cubic B-spline segment on [t_i, t_{i+1}]:
//   S(u) = 1/6 [ (1-u)^3 c0 + (3u^3-6u^2+4) c1 + (-3u^3+3u^2+3u+1) c2 + u^3 c3 ]
// with c0..c3 = coef[i-3 .. i].
// Expanded:
//   a = (-c0 + 3c1 - 3c2 + c3)/6
//   b = ( 3c0 - 6c1 + 3c2     )/6
//   c = (-3c0        + 3c2    )/6
//   d = (  c0 + 4c1 +  c2     )/6
// ---------------------------------------------------------------------------
__global__ void build_poly_kernel(const float* __restrict__ coef) {
    int iv = threadIdx.x;           // 0..6 -> knot interval i = iv+3
    if (iv < 7) {
        float c0 = coef[iv + 0];
        float c1 = coef[iv + 1];
        float c2 = coef[iv + 2];
        float c3 = coef[iv + 3];
        const float s = 1.0f / 6.0f;
        float4 p;
        p.x = (-c0 + 3.0f * c1 - 3.0f * c2 + c3) * s;  // u^3
        p.y = ( 3.0f * c0 - 6.0f * c1 + 3.0f * c2) * s; // u^2
        p.z = (-3.0f * c0 + 3.0f * c2) * s;             // u^1
        p.w = ( c0 + 4.0f * c1 + c2) * s;               // u^0
        g_poly[iv] = p;
    }
}

// ---------------------------------------------------------------------------
// Main elementwise kernel: out = w_basis * silu(x) + w_spline * spline(x)
// ---------------------------------------------------------------------------
__device__ __forceinline__ float eval_one(float x, float wb, float ws,
                                          const float4* __restrict__ sPoly) {
    float fi = x * 13.0f;
    int i = (int)fi;                       // x >= 0 here; truncation == floor
    i = min(max(i, 3), 9);                 // scipy-style clip -> poly extrapolation
    float u = fi - (float)i;
    float4 p = sPoly[i - 3];
    float spline = fmaf(fmaf(fmaf(p.x, u, p.y), u, p.z), u, p.w);
    // silu(x) = x * sigmoid(x)
    float sig = 1.0f / (1.0f + __expf(-x));
    return fmaf(wb, x * sig, ws * spline);
}

__global__ void __launch_bounds__(256)
residual_act_kernel(const float4* __restrict__ x4,
                    const float* __restrict__ w_basis,
                    const float* __restrict__ w_spline,
                    float4* __restrict__ out4,
                    int n4) {
    __shared__ float4 sPoly[7];
    if (threadIdx.x < 7) sPoly[threadIdx.x] = g_poly[threadIdx.x];
    __syncthreads();

    float wb = __ldg(w_basis);
    float ws = __ldg(w_spline);

    int idx = blockIdx.x * blockDim.x + threadIdx.x;
    if (idx >= n4) return;

    float4 xv = x4[idx];
    float4 ov;
    ov.x = eval_one(xv.x, wb, ws, sPoly);
    ov.y = eval_one(xv.y, wb, ws, sPoly);
    ov.z = eval_one(xv.z, wb, ws, sPoly);
    ov.w = eval_one(xv.w, wb, ws, sPoly);
    out4[idx] = ov;
}

// Scalar tail (n not divisible by 4 — defensive; n = 2^24 in practice).
__global__ void residual_act_tail_kernel(const float* __restrict__ x,
                                         const float* __restrict__ w_basis,
                                         const float* __restrict__ w_spline,
                                         float* __restrict__ out,
                                         int start, int n) {
    __shared__ float4 sPoly[7];
    if (threadIdx.x < 7) sPoly[threadIdx.x] = g_poly[threadIdx.x];
    __syncthreads();
    float wb = __ldg(w_basis);
    float ws = __ldg(w_spline);
    int idx = start + blockIdx.x * blockDim.x + threadIdx.x;
    if (idx < n) out[idx] = eval_one(x[idx], wb, ws, sPoly);
}

extern "C" void kernel_launch(void* const* d_in, const int* in_sizes, int n_in,
                              void* d_out, int out_size) {
    const float* x    = (const float*)d_in[0];   // [N] activations
    const float* coef = (const float*)d_in[1];   // [10] spline coefficients
    const float* wb   = (const float*)d_in[2];   // [1] w_basis
    const float* ws   = (const float*)d_in[3];   // [1] w_spline
    float* out        = (float*)d_out;

    int n  = in_sizes[0];
    int n4 = n / 4;

    build_poly_kernel<<<1, 32>>>(coef);

    if (n4 > 0) {
        int threads = 256;
        int blocks  = (n4 + threads - 1) / threads;
        residual_act_kernel<<<blocks, threads>>>(
            (const float4*)x, wb, ws, (float4*)out, n4);
    }
    int tail = n - n4 * 4;
    if (tail > 0) {
        residual_act_tail_kernel<<<1, 256>>>(x, wb, ws, out, n4 * 4, n);
    }
}

// round 2
// speedup vs baseline: 1.2380x; 1.2380x over previous
#include <cuda_runtime.h>
#include <math.h>

// Per-interval cubic polynomial coefficients for the uniform-knot B-spline.
// 7 intervals (knot index i in [3,9]); S(u) = ((a*u+b)*u+c)*u+d, u = 13x - i.
__device__ float4 g_poly[7];

__global__ void build_poly_kernel(const float* __restrict__ coef) {
    int iv = threadIdx.x;           // 0..6 -> knot interval i = iv+3
    if (iv < 7) {
        float c0 = coef[iv + 0];
        float c1 = coef[iv + 1];
        float c2 = coef[iv + 2];
        float c3 = coef[iv + 3];
        const float s = 1.0f / 6.0f;
        float4 p;
        p.x = (-c0 + 3.0f * c1 - 3.0f * c2 + c3) * s;   // u^3
        p.y = ( 3.0f * c0 - 6.0f * c1 + 3.0f * c2) * s; // u^2
        p.z = (-3.0f * c0 + 3.0f * c2) * s;             // u^1
        p.w = ( c0 + 4.0f * c1 + c2) * s;               // u^0
        g_poly[iv] = p;
    }
}

__device__ __forceinline__ float eval_one(float x, float wb, float ws,
                                          const float4* __restrict__ sPoly) {
    float fi = x * 13.0f;
    int i = (int)fi;                       // x >= 0: truncation == floor
    i = min(max(i, 3), 9);                 // scipy clip -> poly extrapolation
    float u = fi - (float)i;
    float4 p = sPoly[i - 3];               // conflict-free: 7 entries, distinct banks
    float spline = fmaf(fmaf(fmaf(p.x, u, p.y), u, p.z), u, p.w);
    float sig = 1.0f / (1.0f + __expf(-x));  // MUFU.EX2 + MUFU.RCP (fast math)
    return fmaf(wb, x * sig, ws * spline);
}

#define V_PER_THREAD 4   // float4s per thread -> 64 B, MLP=4

__global__ void __launch_bounds__(256)
residual_act_kernel(const float4* __restrict__ x4,
                    const float* __restrict__ w_basis,
                    const float* __restrict__ w_spline,
                    float4* __restrict__ out4,
                    int n4) {
    __shared__ float4 sPoly[7];
    if (threadIdx.x < 7) sPoly[threadIdx.x] = g_poly[threadIdx.x];
    __syncthreads();

    float wb = __ldg(w_basis);
    float ws = __ldg(w_spline);

    int base = blockIdx.x * (blockDim.x * V_PER_THREAD) + threadIdx.x;

    // Fast path: whole tile in range -> 4 independent loads issued back-to-back
    if (base + 3 * blockDim.x < n4) {
        float4 xv[V_PER_THREAD];
        #pragma unroll
        for (int k = 0; k < V_PER_THREAD; k++)
            xv[k] = x4[base + k * 256];

        #pragma unroll
        for (int k = 0; k < V_PER_THREAD; k++) {
            float4 ov;
            ov.x = eval_one(xv[k].x, wb, ws, sPoly);
            ov.y = eval_one(xv[k].y, wb, ws, sPoly);
            ov.z = eval_one(xv[k].z, wb, ws, sPoly);
            ov.w = eval_one(xv[k].w, wb, ws, sPoly);
            out4[base + k * 256] = ov;
        }
    } else {
        #pragma unroll
        for (int k = 0; k < V_PER_THREAD; k++) {
            int idx = base + k * 256;
            if (idx < n4) {
                float4 xv = x4[idx];
                float4 ov;
                ov.x = eval_one(xv.x, wb, ws, sPoly);
                ov.y = eval_one(xv.y, wb, ws, sPoly);
                ov.z = eval_one(xv.z, wb, ws, sPoly);
                ov.w = eval_one(xv.w, wb, ws, sPoly);
                out4[idx] = ov;
            }
        }
    }
}

// Scalar tail (n not divisible by 4 — defensive; n = 2^24 in practice).
__global__ void residual_act_tail_kernel(const float* __restrict__ x,
                                         const float* __restrict__ w_basis,
                                         const float* __restrict__ w_spline,
                                         float* __restrict__ out,
                                         int start, int n) {
    __shared__ float4 sPoly[7];
    if (threadIdx.x < 7) sPoly[threadIdx.x] = g_poly[threadIdx.x];
    __syncthreads();
    float wb = __ldg(w_basis);
    float ws = __ldg(w_spline);
    int idx = start + blockIdx.x * blockDim.x + threadIdx.x;
    if (idx < n) out[idx] = eval_one(x[idx], wb, ws, sPoly);
}

extern "C" void kernel_launch(void* const* d_in, const int* in_sizes, int n_in,
                              void* d_out, int out_size) {
    const float* x    = (const float*)d_in[0];   // [N] activations
    const float* coef = (const float*)d_in[1];   // [10] spline coefficients
    const float* wb   = (const float*)d_in[2];   // [1] w_basis
    const float* ws   = (const float*)d_in[3];   // [1] w_spline
    float* out        = (float*)d_out;

    int n  = in_sizes[0];
    int n4 = n / 4;

    build_poly_kernel<<<1, 32>>>(coef);

    if (n4 > 0) {
        int threads = 256;
        int per_block = threads * V_PER_THREAD;
        int blocks = (n4 + per_block - 1) / per_block;
        residual_act_kernel<<<blocks, threads>>>(
            (const float4*)x, wb, ws, (float4*)out, n4);
    }
    int tail = n - n4 * 4;
    if (tail > 0) {
        residual_act_tail_kernel<<<1, 256>>>(x, wb, ws, out, n4 * 4, n);
    }
}